// round 4
// baseline (speedup 1.0000x reference)
#include <cuda_runtime.h>

#define NEGINF __int_as_float(0xff800000)

// Problem constants
#define B_ 8
#define C_ 64
#define H_ 64
#define W_ 64
#define O_ 64
#define CC 16   // channel chunk held in smem

// Block: 64 threads.
//   og      = tid >> 4      (0..3)  -> handles o_local = og*4 .. og*4+3
//   h_local = (tid >> 3)&1  (0..1)  -> output row within 2-row tile
//   wq      = tid & 7       (0..7)  -> output cols wq*8 .. wq*8+7
// Block covers: one b, h-tile of 2 rows, full W=64, o-tile of 16.
// Grid: (32 h-tiles, 4 o-tiles, 8 batch) = 1024 blocks.

__global__ __launch_bounds__(64) void maxplus_conv_kernel(
    const float* __restrict__ x,
    const float* __restrict__ kern,
    float* __restrict__ out)
{
    __shared__ __align__(16) float xs[CC][4][68];   // [cc][row][col] col 0..65 valid, stride 68 for 16B align
    __shared__ __align__(16) float ks[9][CC][16];   // [tap][cc][o_local]

    const int tid = threadIdx.x;
    const int og      = tid >> 4;
    const int h_local = (tid >> 3) & 1;
    const int wq      = tid & 7;

    const int h0 = blockIdx.x * 2;
    const int o0 = blockIdx.y * 16;
    const int b  = blockIdx.z;

    float acc[4][8];
#pragma unroll
    for (int oo = 0; oo < 4; oo++)
#pragma unroll
        for (int i = 0; i < 8; i++)
            acc[oo][i] = NEGINF;

    for (int q = 0; q < C_ / CC; q++) {
        const int c0 = q * CC;

        __syncthreads();   // protect xs/ks reuse from previous chunk

        // ---- stage x tile: rows h0-1 .. h0+2, cols -1..64 (as tile cols 0..65), CC channels ----
#pragma unroll 4
        for (int cc = 0; cc < CC; cc++) {
            const float* xp = x + (((size_t)(b * C_ + c0 + cc)) * H_) * W_;
#pragma unroll
            for (int r = 0; r < 4; r++) {
                const int gh = h0 - 1 + r;
                const bool hok = (gh >= 0) && (gh < H_);
                const float* src = xp + gh * W_;
                // col = tid (0..63), global w = col-1
                {
                    const int gw = tid - 1;
                    xs[cc][r][tid] = (hok && gw >= 0) ? src[gw] : NEGINF;
                }
                if (tid < 2) {
                    const int col = 64 + tid;        // 64,65 -> gw 63,64
                    const int gw = col - 1;
                    xs[cc][r][col] = (hok && gw < W_) ? src[gw] : NEGINF;
                }
            }
        }

        // ---- stage kernel chunk: ks[tap][cc][ol] = kern[((o0+ol)*C + c0+cc)*9 + tap] ----
        for (int idx = tid; idx < 9 * CC * 16; idx += 64) {
            const int ol  = idx & 15;
            const int cc  = (idx >> 4) & 15;
            const int tap = idx >> 8;
            ks[tap][cc][ol] = kern[((o0 + ol) * C_ + (c0 + cc)) * 9 + tap];
        }

        __syncthreads();

        // ---- compute: 576 FADD + 576 FMNMX per cc-iter per thread ----
#pragma unroll 1
        for (int cc = 0; cc < CC; cc++) {
            float xr[3][10];
#pragma unroll
            for (int r = 0; r < 3; r++) {
                const float* base = &xs[cc][h_local + r][wq * 8];
                const float4 a = *(const float4*)(base);
                const float4 c4 = *(const float4*)(base + 4);
                xr[r][0] = a.x;  xr[r][1] = a.y;  xr[r][2] = a.z;  xr[r][3] = a.w;
                xr[r][4] = c4.x; xr[r][5] = c4.y; xr[r][6] = c4.z; xr[r][7] = c4.w;
                xr[r][8] = base[8];
                xr[r][9] = base[9];
            }
#pragma unroll
            for (int ki = 0; ki < 3; ki++) {
#pragma unroll
                for (int kj = 0; kj < 3; kj++) {
                    const float4 kv = *(const float4*)&ks[ki * 3 + kj][cc][og * 4];
#pragma unroll
                    for (int i = 0; i < 8; i++) {
                        const float xv = xr[ki][kj + i];
                        acc[0][i] = fmaxf(acc[0][i], xv + kv.x);
                        acc[1][i] = fmaxf(acc[1][i], xv + kv.y);
                        acc[2][i] = fmaxf(acc[2][i], xv + kv.z);
                        acc[3][i] = fmaxf(acc[3][i], xv + kv.w);
                    }
                }
            }
        }
    }

    // ---- write out: out[b][o][h][w], o = o0 + og*4 + oo, h = h0+h_local, w = wq*8 + i ----
    const int h = h0 + h_local;
#pragma unroll
    for (int oo = 0; oo < 4; oo++) {
        const int o = o0 + og * 4 + oo;
        float* dst = out + (((size_t)(b * O_ + o)) * H_ + h) * W_ + wq * 8;
        float4 v0 = make_float4(acc[oo][0], acc[oo][1], acc[oo][2], acc[oo][3]);
        float4 v1 = make_float4(acc[oo][4], acc[oo][5], acc[oo][6], acc[oo][7]);
        *(float4*)(dst)     = v0;
        *(float4*)(dst + 4) = v1;
    }
}

extern "C" void kernel_launch(void* const* d_in, const int* in_sizes, int n_in,
                              void* d_out, int out_size)
{
    const float* x    = (const float*)d_in[0];   // [8,64,64,64]
    const float* kern = (const float*)d_in[1];   // [64,64,3,3]
    float* out        = (float*)d_out;           // [8,64,64,64]

    dim3 grid(H_ / 2, O_ / 16, B_);   // (32, 4, 8) = 1024 blocks
    dim3 block(64);
    maxplus_conv_kernel<<<grid, block>>>(x, kern, out);
}

// round 5
// speedup vs baseline: 1.1631x; 1.1631x over previous
#include <cuda_runtime.h>

#define NEGINF __int_as_float(0xff800000)

// Problem constants
#define B_ 8
#define C_ 64
#define H_ 64
#define W_ 64
#define O_ 64
#define CC 16   // channel chunk held in smem

// Block: 128 threads.
//   wq      = tid & 15      (0..15) -> output cols wq*4 .. wq*4+3
//   h_local = (tid >> 4)&1  (0..1)  -> output row within 2-row tile
//   og      = tid >> 5      (0..3)  -> o_local = og*4 .. og*4+3
// Block covers: one b, h-tile of 2 rows, full W=64, o-tile of 16.
// Grid: (32 h-tiles, 4 o-tiles, 8 batch) = 1024 blocks = 131072 threads
//   -> ~27.7 warps/SM resident in a single wave (latency hiding).

__global__ __launch_bounds__(128) void maxplus_conv_kernel(
    const float* __restrict__ x,
    const float* __restrict__ kern,
    float* __restrict__ out)
{
    __shared__ __align__(16) float xs[CC][4][68];   // [cc][row][col] cols 0..65 valid (col0 = w=-1)
    __shared__ __align__(16) float ks[9][CC][16];   // [tap][cc][o_local]

    const int tid = threadIdx.x;
    const int wq      = tid & 15;
    const int h_local = (tid >> 4) & 1;
    const int og      = tid >> 5;

    const int h0 = blockIdx.x * 2;
    const int o0 = blockIdx.y * 16;
    const int b  = blockIdx.z;

    float acc[4][4];
#pragma unroll
    for (int oo = 0; oo < 4; oo++)
#pragma unroll
        for (int i = 0; i < 4; i++)
            acc[oo][i] = NEGINF;

    // staging decomposition: 64 (cc,r) row-jobs per chunk, 2 jobs in flight
    const int scol = tid & 63;      // column within row-job
    const int rsel = tid >> 6;      // 0..1 selects even/odd job

    for (int q = 0; q < C_ / CC; q++) {
        const int c0 = q * CC;

        __syncthreads();   // protect xs/ks reuse from previous chunk

        // ---- stage x tile: rows h0-1 .. h0+2, cols -1..64 (tile cols 0..65) ----
#pragma unroll 4
        for (int j2 = 0; j2 < (CC * 4) / 2; j2++) {
            const int j  = j2 * 2 + rsel;
            const int cc = j >> 2;
            const int r  = j & 3;
            const int gh = h0 - 1 + r;
            const bool hok = ((unsigned)gh < (unsigned)H_);
            const float* src = x + ((size_t)((b * C_ + c0 + cc) * H_ + gh)) * W_;
            // tile col = scol (0..63), global w = scol-1
            xs[cc][r][scol] = (hok && scol >= 1) ? src[scol - 1] : NEGINF;
            if (scol < 2) {
                const int col = 64 + scol;      // tile cols 64,65 -> gw 63,64
                const int gw  = col - 1;
                xs[cc][r][col] = (hok && gw < W_) ? src[gw] : NEGINF;
            }
        }

        // ---- stage kernel chunk: ks[tap][cc][ol] = kern[((o0+ol)*C + c0+cc)*9 + tap] ----
        for (int idx = tid; idx < 9 * CC * 16; idx += 128) {
            const int ol  = idx & 15;
            const int cc  = (idx >> 4) & 15;
            const int tap = idx >> 8;
            ks[tap][cc][ol] = kern[((o0 + ol) * C_ + (c0 + cc)) * 9 + tap];
        }

        __syncthreads();

        // ---- compute: per cc-iter per thread: 144 FADD + 144 FMNMX, 15 LDS ----
#pragma unroll 1
        for (int cc = 0; cc < CC; cc++) {
            const float* xbase = &xs[cc][h_local][wq * 4];
            const float* kbase = &ks[0][cc][og * 4];
#pragma unroll
            for (int ki = 0; ki < 3; ki++) {
                // load one input row segment (tile cols wq*4 .. wq*4+7), reuse for 3 kj taps
                float xr[8];
                const float4 a  = *(const float4*)(xbase + ki * 68);
                const float4 c4 = *(const float4*)(xbase + ki * 68 + 4);
                xr[0] = a.x;  xr[1] = a.y;  xr[2] = a.z;  xr[3] = a.w;
                xr[4] = c4.x; xr[5] = c4.y; xr[6] = c4.z; xr[7] = c4.w;
#pragma unroll
                for (int kj = 0; kj < 3; kj++) {
                    const float4 kv = *(const float4*)(kbase + (ki * 3 + kj) * (CC * 16));
#pragma unroll
                    for (int i = 0; i < 4; i++) {
                        const float xv = xr[kj + i];
                        acc[0][i] = fmaxf(acc[0][i], xv + kv.x);
                        acc[1][i] = fmaxf(acc[1][i], xv + kv.y);
                        acc[2][i] = fmaxf(acc[2][i], xv + kv.z);
                        acc[3][i] = fmaxf(acc[3][i], xv + kv.w);
                    }
                }
            }
        }
    }

    // ---- write out: out[b][o][h][w], o = o0 + og*4 + oo, h = h0+h_local, w = wq*4 + i ----
    const int h = h0 + h_local;
#pragma unroll
    for (int oo = 0; oo < 4; oo++) {
        const int o = o0 + og * 4 + oo;
        float* dst = out + (((size_t)(b * O_ + o)) * H_ + h) * W_ + wq * 4;
        *(float4*)dst = make_float4(acc[oo][0], acc[oo][1], acc[oo][2], acc[oo][3]);
    }
}

extern "C" void kernel_launch(void* const* d_in, const int* in_sizes, int n_in,
                              void* d_out, int out_size)
{
    const float* x    = (const float*)d_in[0];   // [8,64,64,64]
    const float* kern = (const float*)d_in[1];   // [64,64,3,3]
    float* out        = (float*)d_out;           // [8,64,64,64]

    dim3 grid(H_ / 2, O_ / 16, B_);   // (32, 4, 8) = 1024 blocks
    dim3 block(128);
    maxplus_conv_kernel<<<grid, block>>>(x, kern, out);
}

// round 7
// speedup vs baseline: 1.4590x; 1.2545x over previous
#include <cuda_runtime.h>

#define NEGINF __int_as_float(0xff800000)

// Problem constants
#define B_ 8
#define C_ 64
#define H_ 64
#define W_ 64
#define O_ 64
#define CC 16   // channel chunk held in smem

// Block: 256 threads.
//   wq      = tid & 31      (0..31) -> output cols wq*2 .. wq*2+1
//   h_local = (tid >> 5)&1  (0..1)  -> output row within 2-row tile
//   og      = tid >> 6      (0..3)  -> o_local = og*4 .. og*4+3
// Block covers: one b, h-tile of 2 rows, full W=64, o-tile of 16 (2048 outputs).
// Grid: (32 h-tiles, 4 o-tiles, 8 batch) = 1024 blocks = 262144 threads
//   -> ~55 warps/SM resident in a single wave.

__global__ __launch_bounds__(256) void maxplus_conv_kernel(
    const float* __restrict__ x,
    const float* __restrict__ kern,
    float* __restrict__ out)
{
    __shared__ __align__(16) float xs[CC][4][68];   // [cc][row][col] cols 0..65 valid (col0 = w=-1)
    __shared__ __align__(16) float ks[9][CC][16];   // [tap][cc][o_local]

    const int tid = threadIdx.x;
    const int wq      = tid & 31;
    const int h_local = (tid >> 5) & 1;
    const int og      = tid >> 6;

    const int h0 = blockIdx.x * 2;
    const int o0 = blockIdx.y * 16;
    const int b  = blockIdx.z;

    float acc[4][2];
#pragma unroll
    for (int oo = 0; oo < 4; oo++) {
        acc[oo][0] = NEGINF;
        acc[oo][1] = NEGINF;
    }

    // staging decomposition: 64 (cc,r) row-jobs per chunk, 4 jobs in flight
    const int scol = tid & 63;      // column within row-job
    const int rsel = tid >> 6;      // 0..3 selects job within group of 4

    for (int q = 0; q < C_ / CC; q++) {
        const int c0 = q * CC;

        __syncthreads();   // protect xs/ks reuse from previous chunk

        // ---- stage x tile: rows h0-1 .. h0+2, cols -1..64 (tile cols 0..65) ----
#pragma unroll 4
        for (int j4 = 0; j4 < (CC * 4) / 4; j4++) {
            const int j  = j4 * 4 + rsel;
            const int cc = j >> 2;
            const int r  = j & 3;
            const int gh = h0 - 1 + r;
            const bool hok = ((unsigned)gh < (unsigned)H_);
            const float* src = x + ((size_t)((b * C_ + c0 + cc) * H_ + gh)) * W_;
            // tile col = scol (0..63), global w = scol-1
            xs[cc][r][scol] = (hok && scol >= 1) ? src[scol - 1] : NEGINF;
            if (scol < 2) {
                const int col = 64 + scol;      // tile cols 64,65 -> gw 63,64
                const int gw  = col - 1;
                xs[cc][r][col] = (hok && gw < W_) ? src[gw] : NEGINF;
            }
        }

        // ---- stage kernel chunk: ks[tap][cc][ol] = kern[((o0+ol)*C + c0+cc)*9 + tap] ----
        for (int idx = tid; idx < 9 * CC * 16; idx += 256) {
            const int ol  = idx & 15;
            const int cc  = (idx >> 4) & 15;
            const int tap = idx >> 8;
            ks[tap][cc][ol] = kern[((o0 + ol) * C_ + (c0 + cc)) * 9 + tap];
        }

        __syncthreads();

        // ---- compute: per cc-iter per thread: 72 FADD + 72 FMNMX, 15 LDS ----
#pragma unroll 2
        for (int cc = 0; cc < CC; cc++) {
            const float* xbase = &xs[cc][h_local][wq * 2];
            const float* kbase = &ks[0][cc][og * 4];
#pragma unroll
            for (int ki = 0; ki < 3; ki++) {
                // load input row segment (tile cols wq*2 .. wq*2+3), reuse for 3 kj taps
                float xr[4];
                const float2 a0 = *(const float2*)(xbase + ki * 68);
                const float2 a1 = *(const float2*)(xbase + ki * 68 + 2);
                xr[0] = a0.x; xr[1] = a0.y; xr[2] = a1.x; xr[3] = a1.y;
#pragma unroll
                for (int kj = 0; kj < 3; kj++) {
                    const float4 kv = *(const float4*)(kbase + (ki * 3 + kj) * (CC * 16));
#pragma unroll
                    for (int i = 0; i < 2; i++) {
                        const float xv = xr[kj + i];
                        acc[0][i] = fmaxf(acc[0][i], xv + kv.x);
                        acc[1][i] = fmaxf(acc[1][i], xv + kv.y);
                        acc[2][i] = fmaxf(acc[2][i], xv + kv.z);
                        acc[3][i] = fmaxf(acc[3][i], xv + kv.w);
                    }
                }
            }
        }
    }

    // ---- write out: out[b][o][h][w], o = o0 + og*4 + oo, h = h0+h_local, w = wq*2 + i ----
    const int h = h0 + h_local;
#pragma unroll
    for (int oo = 0; oo < 4; oo++) {
        const int o = o0 + og * 4 + oo;
        float* dst = out + (((size_t)(b * O_ + o)) * H_ + h) * W_ + wq * 2;
        *(float2*)dst = make_float2(acc[oo][0], acc[oo][1]);
    }
}

extern "C" void kernel_launch(void* const* d_in, const int* in_sizes, int n_in,
                              void* d_out, int out_size)
{
    const float* x    = (const float*)d_in[0];   // [8,64,64,64]
    const float* kern = (const float*)d_in[1];   // [64,64,3,3]
    float* out        = (float*)d_out;           // [8,64,64,64]

    dim3 grid(H_ / 2, O_ / 16, B_);   // (32, 4, 8) = 1024 blocks
    dim3 block(256);
    maxplus_conv_kernel<<<grid, block>>>(x, kern, out);
}